// round 2
// baseline (speedup 1.0000x reference)
#include <cuda_runtime.h>

// Problem constants (fixed by the dataset)
#define N_NODES_MAX 50000
#define E_MAX       550000
#define B_MAX       4096
#define F           128
#define H           512

// Scratch (static device globals — no allocation allowed)
__device__ int   g_flag[N_NODES_MAX];     // 0 = unmarked, else slot+1
__device__ int   g_deg[B_MAX];            // in-degree per slot
__device__ float g_accum[B_MAX * F];      // neighbor feature sums per slot
__device__ int   g_count;                 // active-edge count
__device__ int   g_esrc[E_MAX];           // compacted active edges: src node
__device__ int   g_eslot[E_MAX];          // compacted active edges: dst slot
__device__ float g_h[B_MAX * F];          // dense h_neigh rows for the GEMM

// ---------------------------------------------------------------------------
// K0: reset all scratch touched this launch
__global__ void k_reset(int n_nodes) {
    int i = blockIdx.x * blockDim.x + threadIdx.x;
    int stride = gridDim.x * blockDim.x;
    for (int idx = i; idx < B_MAX * F; idx += stride) g_accum[idx] = 0.0f;
    for (int idx = i; idx < n_nodes; idx += stride) g_flag[idx] = 0;
    for (int idx = i; idx < B_MAX; idx += stride) g_deg[idx] = 0;
    if (i == 0) g_count = 0;
}

// K1: mark id nodes with their slot (+1). Duplicate ids: arbitrary winner,
// but all subsequent readers use the same winner, so result is consistent.
__global__ void k_mark(const int* __restrict__ ids, int nb) {
    int i = blockIdx.x * blockDim.x + threadIdx.x;
    if (i < nb) g_flag[ids[i]] = i + 1;
}

// K2: scan all edges; count degree and compact edges landing on marked nodes
__global__ void k_scan(const int* __restrict__ src, const int* __restrict__ dst, int ne) {
    int i = blockIdx.x * blockDim.x + threadIdx.x;
    if (i >= ne) return;
    int d = dst[i];
    int f = g_flag[d];
    if (f > 0) {
        int slot = f - 1;
        atomicAdd(&g_deg[slot], 1);
        int idx = atomicAdd(&g_count, 1);
        g_esrc[idx]  = src[i];
        g_eslot[idx] = slot;
    }
}

// K3: warp per active edge; scatter-add feat[src] into accum[slot]
__global__ void k_scatter(const float* __restrict__ feat) {
    int gtid  = blockIdx.x * blockDim.x + threadIdx.x;
    int warp  = gtid >> 5;
    int lane  = threadIdx.x & 31;
    int nwarp = (gridDim.x * blockDim.x) >> 5;
    int cnt = g_count;
    for (int e = warp; e < cnt; e += nwarp) {
        int s    = g_esrc[e];
        int slot = g_eslot[e];
        const float4* fr = (const float4*)(feat + (size_t)s * F);
        float* acc = g_accum + (size_t)slot * F;
        float4 v = fr[lane];            // 32 lanes x float4 = 128 floats
        atomicAdd(acc + lane * 4 + 0, v.x);
        atomicAdd(acc + lane * 4 + 1, v.y);
        atomicAdd(acc + lane * 4 + 2, v.z);
        atomicAdd(acc + lane * 4 + 3, v.w);
    }
}

// K4: h_neigh rows for each output index: (neigh_sum + feat[v]) / (deg + 1)
__global__ void k_h(const float* __restrict__ feat, const int* __restrict__ ids, int nb) {
    int idx = blockIdx.x * blockDim.x + threadIdx.x;
    if (idx >= nb * F) return;
    int i = idx >> 7;          // output row
    int k = idx & (F - 1);     // feature
    int node = ids[i];
    int slot = g_flag[node] - 1;
    float inv = 1.0f / (float)(g_deg[slot] + 1);
    g_h[idx] = (g_accum[(size_t)slot * F + k] + feat[(size_t)node * F + k]) * inv;
}

// K5: out[i][j] = tanh( sum_k h[i][k] * W[j][k] + bias[j] )
// M=nb(4096), N=H(512), K=F(128). BM=BN=64, BK=32, 4x4 per-thread tile.
__global__ void k_gemm(const float* __restrict__ W, const float* __restrict__ bias,
                       float* __restrict__ out) {
    __shared__ float As[32][65];
    __shared__ float Bs[32][65];

    int tx = threadIdx.x & 15;   // 0..15 -> cols
    int ty = threadIdx.x >> 4;   // 0..15 -> rows
    int rowBase = blockIdx.y * 64;
    int colBase = blockIdx.x * 64;

    float acc[4][4];
    #pragma unroll
    for (int i = 0; i < 4; i++)
        #pragma unroll
        for (int j = 0; j < 4; j++) acc[i][j] = 0.0f;

    for (int k0 = 0; k0 < F; k0 += 32) {
        // 64 rows x 32 cols per tile = 512 float4; 256 threads x 2
        #pragma unroll
        for (int l = 0; l < 2; l++) {
            int t  = threadIdx.x + l * 256;
            int r  = t >> 3;      // 0..63
            int c4 = t & 7;       // 0..7
            float4 v = *(const float4*)(g_h + (size_t)(rowBase + r) * F + k0 + c4 * 4);
            As[c4 * 4 + 0][r] = v.x;
            As[c4 * 4 + 1][r] = v.y;
            As[c4 * 4 + 2][r] = v.z;
            As[c4 * 4 + 3][r] = v.w;
            float4 w = *(const float4*)(W + (size_t)(colBase + r) * F + k0 + c4 * 4);
            Bs[c4 * 4 + 0][r] = w.x;
            Bs[c4 * 4 + 1][r] = w.y;
            Bs[c4 * 4 + 2][r] = w.z;
            Bs[c4 * 4 + 3][r] = w.w;
        }
        __syncthreads();

        #pragma unroll
        for (int kk = 0; kk < 32; kk++) {
            float a[4], b[4];
            #pragma unroll
            for (int i = 0; i < 4; i++) a[i] = As[kk][ty * 4 + i];
            #pragma unroll
            for (int j = 0; j < 4; j++) b[j] = Bs[kk][tx * 4 + j];
            #pragma unroll
            for (int i = 0; i < 4; i++)
                #pragma unroll
                for (int j = 0; j < 4; j++)
                    acc[i][j] += a[i] * b[j];
        }
        __syncthreads();
    }

    #pragma unroll
    for (int i = 0; i < 4; i++) {
        int r = rowBase + ty * 4 + i;
        #pragma unroll
        for (int j = 0; j < 4; j++) {
            int c = colBase + tx * 4 + j;
            out[(size_t)r * H + c] = tanhf(acc[i][j] + bias[c]);
        }
    }
}

// ---------------------------------------------------------------------------
extern "C" void kernel_launch(void* const* d_in, const int* in_sizes, int n_in,
                              void* d_out, int out_size) {
    const float* feat = (const float*)d_in[0];   // [N, 128]
    const float* W    = (const float*)d_in[1];   // [512, 128]
    const float* bias = (const float*)d_in[2];   // [512]
    const int*   src  = (const int*)d_in[3];     // [E]
    const int*   dst  = (const int*)d_in[4];     // [E]
    const int*   ids  = (const int*)d_in[5];     // [B]

    int n_nodes = in_sizes[0] / F;
    int ne      = in_sizes[3];
    int nb      = in_sizes[5];

    k_reset<<<256, 256>>>(n_nodes);
    k_mark<<<(nb + 255) / 256, 256>>>(ids, nb);
    k_scan<<<(ne + 255) / 256, 256>>>(src, dst, ne);
    k_scatter<<<512, 256>>>(feat);
    k_h<<<(nb * F + 255) / 256, 256>>>(feat, ids, nb);
    dim3 ggrid(H / 64, nb / 64);
    k_gemm<<<ggrid, 256>>>(W, bias, (float*)d_out);
}

// round 3
// speedup vs baseline: 1.1888x; 1.1888x over previous
#include <cuda_runtime.h>

// Problem constants (fixed by the dataset)
#define N_NODES_MAX 50000
#define E_MAX       550000
#define B_MAX       4096
#define F           128
#define H           512

// Scratch (static device globals — no allocation allowed)
__device__ int   g_flag[N_NODES_MAX];     // 0 = unmarked, else slot+1
__device__ int   g_deg[B_MAX];            // in-degree per slot
__device__ int   g_start[B_MAX];          // CSR start per slot
__device__ int   g_cursor[B_MAX];         // CSR fill cursor per slot
__device__ int   g_count;                 // active-edge count
__device__ int   g_esrc[E_MAX];           // compacted active edges: src node
__device__ int   g_eslot[E_MAX];          // compacted active edges: dst slot
__device__ int   g_bsrc[E_MAX];           // CSR-bucketed src nodes
__device__ float g_h[B_MAX * F];          // dense h_neigh rows for the GEMM

// ---------------------------------------------------------------------------
// K0: reset scratch (no more 2MB accum zeroing)
__global__ void k_reset(int n_nodes) {
    int i = blockIdx.x * blockDim.x + threadIdx.x;
    int stride = gridDim.x * blockDim.x;
    for (int idx = i; idx < n_nodes; idx += stride) g_flag[idx] = 0;
    for (int idx = i; idx < B_MAX; idx += stride) g_deg[idx] = 0;
    if (i == 0) g_count = 0;
}

// K1: mark id nodes with their slot (+1). Duplicate ids: arbitrary winner,
// all readers resolve through g_flag so result is consistent.
__global__ void k_mark(const int* __restrict__ ids, int nb) {
    int i = blockIdx.x * blockDim.x + threadIdx.x;
    if (i < nb) g_flag[ids[i]] = i + 1;
}

// K2: scan all edges; count degree and compact edges landing on marked nodes
__global__ void k_scan(const int* __restrict__ src, const int* __restrict__ dst, int ne) {
    int i = blockIdx.x * blockDim.x + threadIdx.x;
    if (i >= ne) return;
    int d = dst[i];
    int f = g_flag[d];
    if (f > 0) {
        int slot = f - 1;
        atomicAdd(&g_deg[slot], 1);
        int idx = atomicAdd(&g_count, 1);
        g_esrc[idx]  = src[i];
        g_eslot[idx] = slot;
    }
}

// K3: exclusive prefix scan over g_deg[B_MAX] -> g_start, g_cursor.
// One block, 1024 threads, 4 elements/thread.
__global__ void k_prefix() {
    __shared__ int warp_tot[32];
    int t = threadIdx.x;
    int d0 = g_deg[4 * t + 0];
    int d1 = g_deg[4 * t + 1];
    int d2 = g_deg[4 * t + 2];
    int d3 = g_deg[4 * t + 3];
    int tot = d0 + d1 + d2 + d3;

    // warp inclusive scan of tot
    int lane = t & 31;
    int wid  = t >> 5;
    int v = tot;
    #pragma unroll
    for (int ofs = 1; ofs < 32; ofs <<= 1) {
        int n = __shfl_up_sync(0xffffffff, v, ofs);
        if (lane >= ofs) v += n;
    }
    if (lane == 31) warp_tot[wid] = v;
    __syncthreads();
    if (wid == 0) {
        int w = (lane < 32) ? warp_tot[lane] : 0;
        #pragma unroll
        for (int ofs = 1; ofs < 32; ofs <<= 1) {
            int n = __shfl_up_sync(0xffffffff, w, ofs);
            if (lane >= ofs) w += n;
        }
        warp_tot[lane] = w;
    }
    __syncthreads();
    int warp_ofs = (wid > 0) ? warp_tot[wid - 1] : 0;
    int excl = warp_ofs + v - tot;   // exclusive start for this thread's 4

    int s0 = excl;
    int s1 = s0 + d0;
    int s2 = s1 + d1;
    int s3 = s2 + d2;
    g_start[4 * t + 0] = s0;  g_cursor[4 * t + 0] = s0;
    g_start[4 * t + 1] = s1;  g_cursor[4 * t + 1] = s1;
    g_start[4 * t + 2] = s2;  g_cursor[4 * t + 2] = s2;
    g_start[4 * t + 3] = s3;  g_cursor[4 * t + 3] = s3;
}

// K4: bucket compacted edges into CSR order (grid-stride; count is dynamic)
__global__ void k_bucket() {
    int cnt = g_count;
    int i = blockIdx.x * blockDim.x + threadIdx.x;
    int stride = gridDim.x * blockDim.x;
    for (; i < cnt; i += stride) {
        int slot = g_eslot[i];
        int pos  = atomicAdd(&g_cursor[slot], 1);
        g_bsrc[pos] = g_esrc[i];
    }
}

// K5: warp per output row: sum CSR neighbor rows in registers, add feat[v],
// scale by 1/(deg+1), write dense g_h row. No atomics.
__global__ void k_slotsum(const float* __restrict__ feat,
                          const int* __restrict__ ids, int nb) {
    int gtid = blockIdx.x * blockDim.x + threadIdx.x;
    int w    = gtid >> 5;
    int lane = threadIdx.x & 31;
    if (w >= nb) return;

    int node = ids[w];
    int slot = g_flag[node] - 1;       // winner slot (handles duplicate ids)
    int start = g_start[slot];
    int deg   = g_deg[slot];
    int end   = start + deg;

    const float4* self = (const float4*)(feat + (size_t)node * F);
    float4 acc = self[lane];           // the "+ feat[v]" term

    int e = start;
    for (; e + 4 <= end; e += 4) {
        int s0 = g_bsrc[e + 0];
        int s1 = g_bsrc[e + 1];
        int s2 = g_bsrc[e + 2];
        int s3 = g_bsrc[e + 3];
        float4 v0 = ((const float4*)(feat + (size_t)s0 * F))[lane];
        float4 v1 = ((const float4*)(feat + (size_t)s1 * F))[lane];
        float4 v2 = ((const float4*)(feat + (size_t)s2 * F))[lane];
        float4 v3 = ((const float4*)(feat + (size_t)s3 * F))[lane];
        acc.x += v0.x + v1.x + v2.x + v3.x;
        acc.y += v0.y + v1.y + v2.y + v3.y;
        acc.z += v0.z + v1.z + v2.z + v3.z;
        acc.w += v0.w + v1.w + v2.w + v3.w;
    }
    for (; e < end; e++) {
        int s = g_bsrc[e];
        float4 v = ((const float4*)(feat + (size_t)s * F))[lane];
        acc.x += v.x; acc.y += v.y; acc.z += v.z; acc.w += v.w;
    }

    float inv = 1.0f / (float)(deg + 1);
    acc.x *= inv; acc.y *= inv; acc.z *= inv; acc.w *= inv;
    ((float4*)(g_h + (size_t)w * F))[lane] = acc;
}

// K6: out[i][j] = tanh( sum_k h[i][k] * W[j][k] + bias[j] )
// M=nb(4096), N=H(512), K=F(128). BM=BN=64, BK=32, 4x4 per-thread tile.
__global__ void k_gemm(const float* __restrict__ W, const float* __restrict__ bias,
                       float* __restrict__ out) {
    __shared__ float As[32][65];
    __shared__ float Bs[32][65];

    int tx = threadIdx.x & 15;   // 0..15 -> cols
    int ty = threadIdx.x >> 4;   // 0..15 -> rows
    int rowBase = blockIdx.y * 64;
    int colBase = blockIdx.x * 64;

    float acc[4][4];
    #pragma unroll
    for (int i = 0; i < 4; i++)
        #pragma unroll
        for (int j = 0; j < 4; j++) acc[i][j] = 0.0f;

    for (int k0 = 0; k0 < F; k0 += 32) {
        #pragma unroll
        for (int l = 0; l < 2; l++) {
            int t  = threadIdx.x + l * 256;
            int r  = t >> 3;      // 0..63
            int c4 = t & 7;       // 0..7
            float4 v = *(const float4*)(g_h + (size_t)(rowBase + r) * F + k0 + c4 * 4);
            As[c4 * 4 + 0][r] = v.x;
            As[c4 * 4 + 1][r] = v.y;
            As[c4 * 4 + 2][r] = v.z;
            As[c4 * 4 + 3][r] = v.w;
            float4 w = *(const float4*)(W + (size_t)(colBase + r) * F + k0 + c4 * 4);
            Bs[c4 * 4 + 0][r] = w.x;
            Bs[c4 * 4 + 1][r] = w.y;
            Bs[c4 * 4 + 2][r] = w.z;
            Bs[c4 * 4 + 3][r] = w.w;
        }
        __syncthreads();

        #pragma unroll
        for (int kk = 0; kk < 32; kk++) {
            float a[4], b[4];
            #pragma unroll
            for (int i = 0; i < 4; i++) a[i] = As[kk][ty * 4 + i];
            #pragma unroll
            for (int j = 0; j < 4; j++) b[j] = Bs[kk][tx * 4 + j];
            #pragma unroll
            for (int i = 0; i < 4; i++)
                #pragma unroll
                for (int j = 0; j < 4; j++)
                    acc[i][j] += a[i] * b[j];
        }
        __syncthreads();
    }

    #pragma unroll
    for (int i = 0; i < 4; i++) {
        int r = rowBase + ty * 4 + i;
        #pragma unroll
        for (int j = 0; j < 4; j++) {
            int c = colBase + tx * 4 + j;
            out[(size_t)r * H + c] = tanhf(acc[i][j] + bias[c]);
        }
    }
}

// ---------------------------------------------------------------------------
extern "C" void kernel_launch(void* const* d_in, const int* in_sizes, int n_in,
                              void* d_out, int out_size) {
    const float* feat = (const float*)d_in[0];   // [N, 128]
    const float* W    = (const float*)d_in[1];   // [512, 128]
    const float* bias = (const float*)d_in[2];   // [512]
    const int*   src  = (const int*)d_in[3];     // [E]
    const int*   dst  = (const int*)d_in[4];     // [E]
    const int*   ids  = (const int*)d_in[5];     // [B]

    int n_nodes = in_sizes[0] / F;
    int ne      = in_sizes[3];
    int nb      = in_sizes[5];

    k_reset<<<128, 256>>>(n_nodes);
    k_mark<<<(nb + 255) / 256, 256>>>(ids, nb);
    k_scan<<<(ne + 255) / 256, 256>>>(src, dst, ne);
    k_prefix<<<1, 1024>>>();
    k_bucket<<<256, 256>>>();
    k_slotsum<<<(nb * 32 + 255) / 256, 256>>>(feat, ids, nb);
    dim3 ggrid(H / 64, (nb + 63) / 64);
    k_gemm<<<ggrid, 256>>>(W, bias, (float*)d_out);
}

// round 4
// speedup vs baseline: 1.5902x; 1.3377x over previous
#include <cuda_runtime.h>

// Problem constants (fixed by the dataset)
#define N_NODES_MAX 50000
#define E_MAX       550000
#define B_MAX       4096
#define F           128
#define H           512
#define CAP         128      // per-slot neighbor bucket capacity (P(deg>128) ~ 0)

// Scratch (static device globals — no allocation allowed)
__device__ int   g_flag[N_NODES_MAX];     // 0 = unmarked, else slot+1
__device__ int   g_deg[B_MAX];            // in-degree per slot (also bucket cursor)
__device__ int   g_bkt[B_MAX * CAP];      // fixed-stride neighbor buckets
__device__ float g_h[B_MAX * F];          // dense h_neigh rows for the GEMM

// ---------------------------------------------------------------------------
// K0: clear node flags only
__global__ void k_reset(int n_nodes) {
    int i = blockIdx.x * blockDim.x + threadIdx.x;
    int stride = gridDim.x * blockDim.x;
    for (int idx = i; idx < n_nodes; idx += stride) g_flag[idx] = 0;
}

// K1: mark id nodes with their slot (+1) AND zero per-slot degree counters.
// Duplicate ids: arbitrary winner; all readers resolve through g_flag, so
// every duplicate row copies the winner slot's data -> consistent output.
__global__ void k_mark(const int* __restrict__ ids, int nb) {
    int i = blockIdx.x * blockDim.x + threadIdx.x;
    if (i < nb) {
        g_flag[ids[i]] = i + 1;
        g_deg[i] = 0;
    }
}

// K2: scan all edges; edges landing on marked nodes go straight into the
// destination slot's fixed-stride bucket (deg counter doubles as cursor).
__global__ void k_scan(const int* __restrict__ src, const int* __restrict__ dst, int ne) {
    int i = blockIdx.x * blockDim.x + threadIdx.x;
    if (i >= ne) return;
    int d = dst[i];
    int f = g_flag[d];
    if (f > 0) {
        int slot = f - 1;
        int pos = atomicAdd(&g_deg[slot], 1);
        if (pos < CAP) g_bkt[slot * CAP + pos] = src[i];
    }
}

// K3: warp per output row: sum bucket neighbor rows in registers, add feat[v],
// scale by 1/(deg+1), write dense g_h row. No atomics.
__global__ void k_slotsum(const float* __restrict__ feat,
                          const int* __restrict__ ids, int nb) {
    int gtid = blockIdx.x * blockDim.x + threadIdx.x;
    int w    = gtid >> 5;
    int lane = threadIdx.x & 31;
    if (w >= nb) return;

    int node = ids[w];
    int slot = g_flag[node] - 1;       // winner slot (handles duplicate ids)
    int deg  = g_deg[slot];
    int cnt  = deg < CAP ? deg : CAP;
    const int* bkt = g_bkt + slot * CAP;

    const float4* self = (const float4*)(feat + (size_t)node * F);
    float4 acc = self[lane];           // the "+ feat[v]" term

    int e = 0;
    for (; e + 4 <= cnt; e += 4) {
        int s0 = bkt[e + 0];
        int s1 = bkt[e + 1];
        int s2 = bkt[e + 2];
        int s3 = bkt[e + 3];
        float4 v0 = ((const float4*)(feat + (size_t)s0 * F))[lane];
        float4 v1 = ((const float4*)(feat + (size_t)s1 * F))[lane];
        float4 v2 = ((const float4*)(feat + (size_t)s2 * F))[lane];
        float4 v3 = ((const float4*)(feat + (size_t)s3 * F))[lane];
        acc.x += v0.x + v1.x + v2.x + v3.x;
        acc.y += v0.y + v1.y + v2.y + v3.y;
        acc.z += v0.z + v1.z + v2.z + v3.z;
        acc.w += v0.w + v1.w + v2.w + v3.w;
    }
    for (; e < cnt; e++) {
        int s = bkt[e];
        float4 v = ((const float4*)(feat + (size_t)s * F))[lane];
        acc.x += v.x; acc.y += v.y; acc.z += v.z; acc.w += v.w;
    }

    float inv = 1.0f / (float)(deg + 1);
    acc.x *= inv; acc.y *= inv; acc.z *= inv; acc.w *= inv;
    ((float4*)(g_h + (size_t)w * F))[lane] = acc;
}

// K4: out[i][j] = tanh( sum_k h[i][k] * W[j][k] + bias[j] )
// M=nb(4096), N=H(512), K=F(128). BM=BN=64, BK=32, 4x4 per-thread tile.
__global__ void k_gemm(const float* __restrict__ W, const float* __restrict__ bias,
                       float* __restrict__ out) {
    __shared__ float As[32][65];
    __shared__ float Bs[32][65];

    int tx = threadIdx.x & 15;   // 0..15 -> cols
    int ty = threadIdx.x >> 4;   // 0..15 -> rows
    int rowBase = blockIdx.y * 64;
    int colBase = blockIdx.x * 64;

    float acc[4][4];
    #pragma unroll
    for (int i = 0; i < 4; i++)
        #pragma unroll
        for (int j = 0; j < 4; j++) acc[i][j] = 0.0f;

    for (int k0 = 0; k0 < F; k0 += 32) {
        #pragma unroll
        for (int l = 0; l < 2; l++) {
            int t  = threadIdx.x + l * 256;
            int r  = t >> 3;      // 0..63
            int c4 = t & 7;       // 0..7
            float4 v = *(const float4*)(g_h + (size_t)(rowBase + r) * F + k0 + c4 * 4);
            As[c4 * 4 + 0][r] = v.x;
            As[c4 * 4 + 1][r] = v.y;
            As[c4 * 4 + 2][r] = v.z;
            As[c4 * 4 + 3][r] = v.w;
            float4 w = *(const float4*)(W + (size_t)(colBase + r) * F + k0 + c4 * 4);
            Bs[c4 * 4 + 0][r] = w.x;
            Bs[c4 * 4 + 1][r] = w.y;
            Bs[c4 * 4 + 2][r] = w.z;
            Bs[c4 * 4 + 3][r] = w.w;
        }
        __syncthreads();

        #pragma unroll
        for (int kk = 0; kk < 32; kk++) {
            float a[4], b[4];
            #pragma unroll
            for (int i = 0; i < 4; i++) a[i] = As[kk][ty * 4 + i];
            #pragma unroll
            for (int j = 0; j < 4; j++) b[j] = Bs[kk][tx * 4 + j];
            #pragma unroll
            for (int i = 0; i < 4; i++)
                #pragma unroll
                for (int j = 0; j < 4; j++)
                    acc[i][j] += a[i] * b[j];
        }
        __syncthreads();
    }

    #pragma unroll
    for (int i = 0; i < 4; i++) {
        int r = rowBase + ty * 4 + i;
        #pragma unroll
        for (int j = 0; j < 4; j++) {
            int c = colBase + tx * 4 + j;
            out[(size_t)r * H + c] = tanhf(acc[i][j] + bias[c]);
        }
    }
}

// ---------------------------------------------------------------------------
extern "C" void kernel_launch(void* const* d_in, const int* in_sizes, int n_in,
                              void* d_out, int out_size) {
    const float* feat = (const float*)d_in[0];   // [N, 128]
    const float* W    = (const float*)d_in[1];   // [512, 128]
    const float* bias = (const float*)d_in[2];   // [512]
    const int*   src  = (const int*)d_in[3];     // [E]
    const int*   dst  = (const int*)d_in[4];     // [E]
    const int*   ids  = (const int*)d_in[5];     // [B]

    int n_nodes = in_sizes[0] / F;
    int ne      = in_sizes[3];
    int nb      = in_sizes[5];

    k_reset<<<128, 256>>>(n_nodes);
    k_mark<<<(nb + 255) / 256, 256>>>(ids, nb);
    k_scan<<<(ne + 255) / 256, 256>>>(src, dst, ne);
    k_slotsum<<<(nb * 32 + 255) / 256, 256>>>(feat, ids, nb);
    dim3 ggrid(H / 64, (nb + 63) / 64);
    k_gemm<<<ggrid, 256>>>(W, bias, (float*)d_out);
}

// round 5
// speedup vs baseline: 2.4434x; 1.5366x over previous
#include <cuda_runtime.h>
#include <cuda_bf16.h>
#include <cstdint>

// Problem constants (fixed by the dataset)
#define N_NODES_MAX 50000
#define E_MAX       550000
#define B_MAX       4096
#define F           128
#define H           512
#define CAP         128      // per-slot neighbor bucket capacity (P(deg>128) ~ 0)

// Scratch (static device globals — no allocation allowed)
__device__ int            g_flag[N_NODES_MAX];   // 0 = unmarked, else slot+1
__device__ int            g_deg[B_MAX];          // in-degree per slot (bucket cursor)
__device__ int            g_bkt[B_MAX * CAP];    // fixed-stride neighbor buckets
__device__ __nv_bfloat16  g_h_hi[B_MAX * F];     // h_neigh split: high bf16
__device__ __nv_bfloat16  g_h_lo[B_MAX * F];     // h_neigh split: low  bf16
__device__ __nv_bfloat16  g_w_hi[H * F];         // W split: high bf16
__device__ __nv_bfloat16  g_w_lo[H * F];         // W split: low  bf16

// ---------------------------------------------------------------------------
// helpers
__device__ __forceinline__ uint32_t smem_u32(const void* p) {
    return (uint32_t)__cvta_generic_to_shared(p);
}
__device__ __forceinline__ uint32_t pack_bf2(__nv_bfloat16 a, __nv_bfloat16 b) {
    __nv_bfloat162 t; t.x = a; t.y = b;
    return *reinterpret_cast<uint32_t*>(&t);
}

#define LDSM_X4(R, PTR)                                                        \
    asm volatile("ldmatrix.sync.aligned.m8n8.x4.shared.b16 {%0,%1,%2,%3}, [%4];" \
                 : "=r"((R)[0]), "=r"((R)[1]), "=r"((R)[2]), "=r"((R)[3])       \
                 : "r"(smem_u32(PTR)))

#define MMA_BF16(C, A, B0, B1)                                                 \
    asm volatile("mma.sync.aligned.m16n8k16.row.col.f32.bf16.bf16.f32 "        \
                 "{%0,%1,%2,%3}, {%4,%5,%6,%7}, {%8,%9}, {%0,%1,%2,%3};"       \
                 : "+f"((C)[0]), "+f"((C)[1]), "+f"((C)[2]), "+f"((C)[3])      \
                 : "r"((A)[0]), "r"((A)[1]), "r"((A)[2]), "r"((A)[3]),         \
                   "r"(B0), "r"(B1))

__device__ __forceinline__ float fast_tanh(float x) {
    asm("tanh.approx.f32 %0, %0;" : "+f"(x));
    return x;
}

// ---------------------------------------------------------------------------
// K0: clear node flags AND split W into bf16 hi/lo (independent work, one launch)
__global__ void k_reset(int n_nodes, const float* __restrict__ W) {
    int i = blockIdx.x * blockDim.x + threadIdx.x;
    int stride = gridDim.x * blockDim.x;
    for (int idx = i; idx < n_nodes; idx += stride) g_flag[idx] = 0;
    for (int idx = i; idx < H * F; idx += stride) {
        float w = W[idx];
        __nv_bfloat16 hi = __float2bfloat16(w);
        g_w_hi[idx] = hi;
        g_w_lo[idx] = __float2bfloat16(w - __bfloat162float(hi));
    }
}

// K1: mark id nodes with their slot (+1) AND zero per-slot degree counters.
__global__ void k_mark(const int* __restrict__ ids, int nb) {
    int i = blockIdx.x * blockDim.x + threadIdx.x;
    if (i < nb) {
        g_flag[ids[i]] = i + 1;
        g_deg[i] = 0;
    }
}

// K2: scan all edges (int4 vectorized); edges landing on marked nodes go
// straight into the destination slot's fixed-stride bucket.
__device__ __forceinline__ void scan_one(int s, int d) {
    int f = g_flag[d];
    if (f > 0) {
        int slot = f - 1;
        int pos = atomicAdd(&g_deg[slot], 1);
        if (pos < CAP) g_bkt[slot * CAP + pos] = s;
    }
}
__global__ void k_scan(const int* __restrict__ src, const int* __restrict__ dst, int ne) {
    int i = blockIdx.x * blockDim.x + threadIdx.x;
    int ne4 = ne >> 2;
    if (i < ne4) {
        int4 s = ((const int4*)src)[i];
        int4 d = ((const int4*)dst)[i];
        scan_one(s.x, d.x);
        scan_one(s.y, d.y);
        scan_one(s.z, d.z);
        scan_one(s.w, d.w);
    }
    int tail = ne & 3;
    if (i < tail) {
        int j = ne - tail + i;
        scan_one(src[j], dst[j]);
    }
}

// K3: warp per output row: sum bucket neighbor rows in registers (unroll-8
// for MLP), add feat[v], scale by 1/(deg+1), write bf16 hi/lo split rows.
__global__ void k_slotsum(const float* __restrict__ feat,
                          const int* __restrict__ ids, int nb) {
    int gtid = blockIdx.x * blockDim.x + threadIdx.x;
    int w    = gtid >> 5;
    int lane = threadIdx.x & 31;
    if (w >= nb) return;

    int node = ids[w];
    int slot = g_flag[node] - 1;       // winner slot (handles duplicate ids)
    int deg  = g_deg[slot];
    int cnt  = deg < CAP ? deg : CAP;
    const int* bkt = g_bkt + slot * CAP;

    float4 acc = ((const float4*)(feat + (size_t)node * F))[lane];  // + feat[v]

    int e = 0;
    for (; e + 8 <= cnt; e += 8) {
        int si[8];
        #pragma unroll
        for (int u = 0; u < 8; u++) si[u] = bkt[e + u];
        float4 v[8];
        #pragma unroll
        for (int u = 0; u < 8; u++)
            v[u] = ((const float4*)(feat + (size_t)si[u] * F))[lane];
        #pragma unroll
        for (int u = 0; u < 8; u++) {
            acc.x += v[u].x; acc.y += v[u].y; acc.z += v[u].z; acc.w += v[u].w;
        }
    }
    for (; e + 4 <= cnt; e += 4) {
        int s0 = bkt[e], s1 = bkt[e+1], s2 = bkt[e+2], s3 = bkt[e+3];
        float4 v0 = ((const float4*)(feat + (size_t)s0 * F))[lane];
        float4 v1 = ((const float4*)(feat + (size_t)s1 * F))[lane];
        float4 v2 = ((const float4*)(feat + (size_t)s2 * F))[lane];
        float4 v3 = ((const float4*)(feat + (size_t)s3 * F))[lane];
        acc.x += v0.x + v1.x + v2.x + v3.x;
        acc.y += v0.y + v1.y + v2.y + v3.y;
        acc.z += v0.z + v1.z + v2.z + v3.z;
        acc.w += v0.w + v1.w + v2.w + v3.w;
    }
    for (; e < cnt; e++) {
        float4 v = ((const float4*)(feat + (size_t)bkt[e] * F))[lane];
        acc.x += v.x; acc.y += v.y; acc.z += v.z; acc.w += v.w;
    }

    float inv = 1.0f / (float)(deg + 1);
    acc.x *= inv; acc.y *= inv; acc.z *= inv; acc.w *= inv;

    // bf16 hi/lo split, 4 values per lane, packed 8B stores
    __nv_bfloat16 hx = __float2bfloat16(acc.x);
    __nv_bfloat16 hy = __float2bfloat16(acc.y);
    __nv_bfloat16 hz = __float2bfloat16(acc.z);
    __nv_bfloat16 hw = __float2bfloat16(acc.w);
    uint2 uh, ul;
    uh.x = pack_bf2(hx, hy);
    uh.y = pack_bf2(hz, hw);
    ul.x = pack_bf2(__float2bfloat16(acc.x - __bfloat162float(hx)),
                    __float2bfloat16(acc.y - __bfloat162float(hy)));
    ul.y = pack_bf2(__float2bfloat16(acc.z - __bfloat162float(hz)),
                    __float2bfloat16(acc.w - __bfloat162float(hw)));
    ((uint2*)(g_h_hi + (size_t)w * F))[lane] = uh;
    ((uint2*)(g_h_lo + (size_t)w * F))[lane] = ul;
}

// K4: tensor-core GEMM with bf16 3-split: out = tanh(h @ W^T + bias).
// BM=BN=64, K=128 in two 64-chunks. 8 warps: warp_m = wid&1 (m32),
// warp_n = wid>>1 (n16). mma.m16n8k16, hi*hi + hi*lo + lo*hi.
__global__ void k_gemm(const float* __restrict__ bias, float* __restrict__ out, int nb) {
    __shared__ __nv_bfloat16 a_hi[64][72], a_lo[64][72];
    __shared__ __nv_bfloat16 b_hi[64][72], b_lo[64][72];

    int tid  = threadIdx.x;
    int wid  = tid >> 5, lane = tid & 31;
    int warp_m = wid & 1, warp_n = wid >> 1;
    int rowBase = blockIdx.y * 64, colBase = blockIdx.x * 64;
    int g8 = lane >> 3, r8 = lane & 7;

    float acc[2][2][4] = {};

    #pragma unroll
    for (int kc = 0; kc < 2; kc++) {
        // stage 64x64 tiles of all four operands (uint4 = 8 bf16)
        #pragma unroll
        for (int l = 0; l < 2; l++) {
            int idx = tid + l * 256;
            int rr = idx >> 3, c8 = (idx & 7) * 8;
            int gc = kc * 64 + c8;
            *(uint4*)&a_hi[rr][c8] = *(const uint4*)&g_h_hi[(size_t)(rowBase + rr) * F + gc];
            *(uint4*)&a_lo[rr][c8] = *(const uint4*)&g_h_lo[(size_t)(rowBase + rr) * F + gc];
            *(uint4*)&b_hi[rr][c8] = *(const uint4*)&g_w_hi[(size_t)(colBase + rr) * F + gc];
            *(uint4*)&b_lo[rr][c8] = *(const uint4*)&g_w_lo[(size_t)(colBase + rr) * F + gc];
        }
        __syncthreads();

        #pragma unroll
        for (int ks = 0; ks < 64; ks += 16) {
            uint32_t ah[2][4], al[2][4], bh[4], bl[4];
            #pragma unroll
            for (int mt = 0; mt < 2; mt++) {
                int row = warp_m * 32 + mt * 16 + (g8 & 1) * 8 + r8;
                int col = ks + (g8 >> 1) * 8;
                LDSM_X4(ah[mt], &a_hi[row][col]);
                LDSM_X4(al[mt], &a_lo[row][col]);
            }
            {
                int brow = warp_n * 16 + (g8 >> 1) * 8 + r8;
                int bcol = ks + (g8 & 1) * 8;
                LDSM_X4(bh, &b_hi[brow][bcol]);
                LDSM_X4(bl, &b_lo[brow][bcol]);
            }
            #pragma unroll
            for (int mt = 0; mt < 2; mt++)
                #pragma unroll
                for (int nt = 0; nt < 2; nt++) {
                    MMA_BF16(acc[mt][nt], ah[mt], bh[2*nt], bh[2*nt+1]);
                    MMA_BF16(acc[mt][nt], ah[mt], bl[2*nt], bl[2*nt+1]);
                    MMA_BF16(acc[mt][nt], al[mt], bh[2*nt], bh[2*nt+1]);
                }
        }
        __syncthreads();
    }

    // epilogue: +bias, tanh, store
    int g = lane >> 2, t = lane & 3;
    #pragma unroll
    for (int mt = 0; mt < 2; mt++) {
        int row0 = rowBase + warp_m * 32 + mt * 16 + g;
        #pragma unroll
        for (int nt = 0; nt < 2; nt++) {
            int col = colBase + warp_n * 16 + nt * 8 + t * 2;
            float2 b = *(const float2*)(bias + col);
            float2 o0, o1;
            o0.x = fast_tanh(acc[mt][nt][0] + b.x);
            o0.y = fast_tanh(acc[mt][nt][1] + b.y);
            o1.x = fast_tanh(acc[mt][nt][2] + b.x);
            o1.y = fast_tanh(acc[mt][nt][3] + b.y);
            if (row0 < nb)     *(float2*)(out + (size_t)row0 * H + col) = o0;
            if (row0 + 8 < nb) *(float2*)(out + (size_t)(row0 + 8) * H + col) = o1;
        }
    }
}

// ---------------------------------------------------------------------------
extern "C" void kernel_launch(void* const* d_in, const int* in_sizes, int n_in,
                              void* d_out, int out_size) {
    const float* feat = (const float*)d_in[0];   // [N, 128]
    const float* W    = (const float*)d_in[1];   // [512, 128]
    const float* bias = (const float*)d_in[2];   // [512]
    const int*   src  = (const int*)d_in[3];     // [E]
    const int*   dst  = (const int*)d_in[4];     // [E]
    const int*   ids  = (const int*)d_in[5];     // [B]

    int n_nodes = in_sizes[0] / F;
    int ne      = in_sizes[3];
    int nb      = in_sizes[5];

    k_reset<<<128, 256>>>(n_nodes, W);
    k_mark<<<(nb + 255) / 256, 256>>>(ids, nb);
    int nthr = (ne + 3) / 4;
    k_scan<<<(nthr + 255) / 256, 256>>>(src, dst, ne);
    k_slotsum<<<(nb * 32 + 255) / 256, 256>>>(feat, ids, nb);
    dim3 ggrid(H / 64, (nb + 63) / 64);
    k_gemm<<<ggrid, 256>>>(bias, (float*)d_out, nb);
}